// round 8
// baseline (speedup 1.0000x reference)
#include <cuda_runtime.h>
#include <cuda_bf16.h>
#include <cuda_fp16.h>
#include <math.h>
#include <stdint.h>

// ---------------- problem constants ----------------
#define B_ 2
#define S_ 2048
#define D_ 2048
#define H_ 16
#define RK 512
#define ROPE_ 64
#define NOPE_ 128
#define QK_HD 192
#define V_HD 128
#define CD 576            // RK + ROPE
#define BS (B_ * S_)      // 4096
#define EPS_ 1.1920929e-07f
#define SCALE_ 0.0721687836487032f

// ---------------- scratch (bf16 hi/lo pair-word arrays + fp16/fp32) ----------------
__device__ uint32_t gs_xh [(size_t)BS * 1024],  gs_xl [(size_t)BS * 1024];   // x pairs
__device__ uint32_t gs_wqh[(size_t)3072 * 1024], gs_wql[(size_t)3072 * 1024];
__device__ uint32_t gs_wah[(size_t)576 * 1024],  gs_wal[(size_t)576 * 1024]; // wkv_a
__device__ uint32_t gs_bTh[(size_t)H_ * 512 * 64], gs_bTl[(size_t)H_ * 512 * 64]; // wkvb nope, transposed (RK x NOPE/2)
__device__ uint32_t gs_bVh[(size_t)H_ * 128 * 256], gs_bVl[(size_t)H_ * 128 * 256]; // wkvb V (V_HD x RK/2)
__device__ uint32_t gs_woh[(size_t)2048 * 1024], gs_wol[(size_t)2048 * 1024];
__device__ uint32_t gs_qh [(size_t)BS * 1536],  gs_ql [(size_t)BS * 1536];   // q proj out pairs
__device__ uint32_t gs_kvh[(size_t)BS * 288],   gs_kvl[(size_t)BS * 288];    // kv_a out pairs
__device__ uint32_t gs_olh[(size_t)BS * 4096],  gs_oll[(size_t)BS * 4096];   // flash out pairs
__device__ uint32_t gs_ovh[(size_t)BS * 1024],  gs_ovl[(size_t)BS * 1024];   // v-up out pairs
__device__ __half   g_qfh [(size_t)BS * H_ * CD];   // flash q (fp16)
__device__ __half   g_kfh [(size_t)BS * CD];        // flash K (fp16, scores)
__device__ float    g_kfv [(size_t)BS * RK];        // flash V (tf32-rounded fp32, PV)

// ---------------- helpers ----------------
__device__ __forceinline__ float tf32r(float x) {
    uint32_t u = __float_as_uint(x), o;
    asm("cvt.rna.tf32.f32 %0, %1;" : "=r"(o) : "r"(u));
    return __uint_as_float(o);
}
__device__ __forceinline__ void split_bf2(float2 p, uint32_t& hi, uint32_t& lo) {
    __nv_bfloat162 h = __float22bfloat162_rn(p);
    float hx = __low2float(h), hy = __high2float(h);
    __nv_bfloat162 l = __float22bfloat162_rn(make_float2(p.x - hx, p.y - hy));
    hi = *(uint32_t*)&h;
    lo = *(uint32_t*)&l;
}
__device__ __forceinline__ float2 up2(uint32_t hw, uint32_t lw) {
    __nv_bfloat162 H = *(__nv_bfloat162*)&hw;
    __nv_bfloat162 L = *(__nv_bfloat162*)&lw;
    return make_float2(__low2float(H) + __low2float(L),
                       __high2float(H) + __high2float(L));
}
__device__ __forceinline__ void mma_bf16(float c[4],
    uint32_t a0, uint32_t a1, uint32_t a2, uint32_t a3, uint32_t b0, uint32_t b1)
{
    asm volatile("mma.sync.aligned.m16n8k16.row.col.f32.bf16.bf16.f32 "
        "{%0,%1,%2,%3}, {%4,%5,%6,%7}, {%8,%9}, {%0,%1,%2,%3};\n"
        : "+f"(c[0]), "+f"(c[1]), "+f"(c[2]), "+f"(c[3])
        : "r"(a0), "r"(a1), "r"(a2), "r"(a3), "r"(b0), "r"(b1));
}
__device__ __forceinline__ void mma_f16(float c[4],
    uint32_t a0, uint32_t a1, uint32_t a2, uint32_t a3, uint32_t b0, uint32_t b1)
{
    asm volatile("mma.sync.aligned.m16n8k16.row.col.f32.f16.f16.f32 "
        "{%0,%1,%2,%3}, {%4,%5,%6,%7}, {%8,%9}, {%0,%1,%2,%3};\n"
        : "+f"(c[0]), "+f"(c[1]), "+f"(c[2]), "+f"(c[3])
        : "r"(a0), "r"(a1), "r"(a2), "r"(a3), "r"(b0), "r"(b1));
}
__device__ __forceinline__ void mma_tf32(float c[4],
    uint32_t a0, uint32_t a1, uint32_t a2, uint32_t a3, uint32_t b0, uint32_t b1)
{
    asm volatile("mma.sync.aligned.m16n8k8.row.col.f32.tf32.tf32.f32 "
        "{%0,%1,%2,%3}, {%4,%5,%6,%7}, {%8,%9}, {%0,%1,%2,%3};\n"
        : "+f"(c[0]), "+f"(c[1]), "+f"(c[2]), "+f"(c[3])
        : "r"(a0), "r"(a1), "r"(a2), "r"(a3), "r"(b0), "r"(b1));
}
__device__ __forceinline__ uint32_t sm_u32(const void* p) {
    return (uint32_t)__cvta_generic_to_shared(p);
}
#define CPA16(d, s) asm volatile("cp.async.ca.shared.global [%0], [%1], 16;\n" :: "r"(d), "l"(s))
#define CPCOMMIT()  asm volatile("cp.async.commit_group;\n")
#define CPWAIT(n)   asm volatile("cp.async.wait_group %0;\n" :: "n"(n))

// ---------------- pre-split kernels ----------------
__global__ __launch_bounds__(256)
void split_pairs(const float2* __restrict__ in, uint32_t* __restrict__ hi,
                 uint32_t* __restrict__ lo, int nw)
{
    int i = blockIdx.x * 256 + threadIdx.x;
    if (i < nw) { uint32_t h, l; split_bf2(in[i], h, l); hi[i] = h; lo[i] = l; }
}
// wkvb nope part -> transposed (per head: RK rows x NOPE/2 pair-words)
__global__ __launch_bounds__(256)
void split_wkvb_nope(const float* __restrict__ w)
{
    int i = blockIdx.x * 256 + threadIdx.x;        // < 16*512*64
    int dw = i & 63, c = (i >> 6) & 511, h = i >> 15;
    const float* base = w + (size_t)h * 131072;
    float2 v = make_float2(base[(2 * dw) * 512 + c], base[(2 * dw + 1) * 512 + c]);
    uint32_t hh, ll; split_bf2(v, hh, ll);
    gs_bTh[i] = hh; gs_bTl[i] = ll;
}
// wkvb v part (per head: V_HD rows x RK/2 pair-words)
__global__ __launch_bounds__(256)
void split_wkvb_v(const float* __restrict__ w)
{
    int i = blockIdx.x * 256 + threadIdx.x;        // < 16*128*256
    int cw = i & 255, d = (i >> 8) & 127, h = i >> 15;
    const float2* src = (const float2*)(w + (size_t)h * 131072 + (size_t)(128 + d) * 512);
    uint32_t hh, ll; split_bf2(src[cw], hh, ll);
    gs_bVh[i] = hh; gs_bVl[i] = ll;
}

// ---------------- bf16 pre-split GEMM (3-term, fp32-grade) ----------------
// C = alpha * A * B^T (+bias). A:(M,K) pair-words [M][Kw]. B:(N,K) pair-words [N][Kw].
// 128x64x16 tile, 3-stage cp.async. OM: 0=f32 out, 1=f16 out, 2=split out.
#define GEMM_SMEM (13824 * 4)
template<int OM, bool HASB>
__global__ __launch_bounds__(256)
void gemm_ps(int Kw,
             const uint32_t* __restrict__ Ah, const uint32_t* __restrict__ Al,
             int ldaw, long aBw,
             const uint32_t* __restrict__ Bh, const uint32_t* __restrict__ Bl,
             int ldbw, long bBw,
             void* C0, void* C1, int ldc, long cB,
             const float* __restrict__ bias, float alpha)
{
    extern __shared__ uint32_t gsm[];
    uint32_t* sAh = gsm;            // 3 * 1536 (pitch 12)
    uint32_t* sAl = gsm + 4608;
    uint32_t* sBh = gsm + 9216;     // 3 * 768
    uint32_t* sBl = gsm + 11520;

    int z = blockIdx.z;
    Ah += (long)z * aBw; Al += (long)z * aBw;
    Bh += (long)z * bBw; Bl += (long)z * bBw;

    long m0 = (long)blockIdx.y * 128;
    long n0 = (long)blockIdx.x * 64;
    int tid = threadIdx.x;
    int w = tid >> 5, lane = tid & 31, gid = lane >> 2, tig = lane & 3;
    int wm = w & 3, wn = w >> 2;

    uint32_t smu = sm_u32(gsm);
    int nk = Kw / 8;

    auto issue = [&](int s, int kt) {
        int kw0 = kt * 8;
        {   // A: 512 chunks (128 rows x 2 x hi/lo); 2 per thread
            int c = tid;                       // hi
            int r = c >> 1, hf = (c & 1) * 4;
            CPA16(smu + (0    + s * 1536 + r * 12 + hf) * 4, &Ah[(m0 + r) * (long)ldaw + kw0 + hf]);
            CPA16(smu + (4608 + s * 1536 + r * 12 + hf) * 4, &Al[(m0 + r) * (long)ldaw + kw0 + hf]);
        }
        {   // B: 256 chunks; 1 per thread
            int c = tid;
            int r = (c & 127) >> 1, hf = (c & 1) * 4;
            if (c < 128)
                CPA16(smu + (9216  + s * 768 + r * 12 + hf) * 4, &Bh[(n0 + r) * (long)ldbw + kw0 + hf]);
            else
                CPA16(smu + (11520 + s * 768 + r * 12 + hf) * 4, &Bl[(n0 + r) * (long)ldbw + kw0 + hf]);
        }
    };

    float acc[2][4][4];
#pragma unroll
    for (int mi = 0; mi < 2; mi++)
#pragma unroll
        for (int j = 0; j < 4; j++)
#pragma unroll
            for (int e = 0; e < 4; e++) acc[mi][j][e] = 0.f;

    issue(0, 0); CPCOMMIT();
    issue(1, 1); CPCOMMIT();

    for (int kt = 0; kt < nk; kt++) {
        CPWAIT(1);
        __syncthreads();
        if (kt + 2 < nk) { issue((kt + 2) % 3, kt + 2); CPCOMMIT(); }

        const uint32_t* cAh = sAh + (kt % 3) * 1536;
        const uint32_t* cAl = sAl + (kt % 3) * 1536;
        const uint32_t* cBh = sBh + (kt % 3) * 768;
        const uint32_t* cBl = sBl + (kt % 3) * 768;

        uint32_t ahi[2][4], alo[2][4], bhi[4][2], blo[4][2];
#pragma unroll
        for (int mi = 0; mi < 2; mi++) {
            int rb = wm * 32 + mi * 16 + gid;
            ahi[mi][0] = cAh[rb * 12 + tig];       alo[mi][0] = cAl[rb * 12 + tig];
            ahi[mi][1] = cAh[(rb + 8) * 12 + tig]; alo[mi][1] = cAl[(rb + 8) * 12 + tig];
            ahi[mi][2] = cAh[rb * 12 + tig + 4];   alo[mi][2] = cAl[rb * 12 + tig + 4];
            ahi[mi][3] = cAh[(rb + 8) * 12 + tig + 4]; alo[mi][3] = cAl[(rb + 8) * 12 + tig + 4];
        }
#pragma unroll
        for (int j = 0; j < 4; j++) {
            int nb = wn * 32 + j * 8 + gid;
            bhi[j][0] = cBh[nb * 12 + tig];     blo[j][0] = cBl[nb * 12 + tig];
            bhi[j][1] = cBh[nb * 12 + tig + 4]; blo[j][1] = cBl[nb * 12 + tig + 4];
        }
#pragma unroll
        for (int mi = 0; mi < 2; mi++)
#pragma unroll
            for (int j = 0; j < 4; j++) {
                mma_bf16(acc[mi][j], ahi[mi][0], ahi[mi][1], ahi[mi][2], ahi[mi][3],
                         blo[j][0], blo[j][1]);
                mma_bf16(acc[mi][j], alo[mi][0], alo[mi][1], alo[mi][2], alo[mi][3],
                         bhi[j][0], bhi[j][1]);
                mma_bf16(acc[mi][j], ahi[mi][0], ahi[mi][1], ahi[mi][2], ahi[mi][3],
                         bhi[j][0], bhi[j][1]);
            }
        __syncthreads();
    }

#pragma unroll
    for (int mi = 0; mi < 2; mi++) {
#pragma unroll
        for (int j = 0; j < 4; j++) {
            long col = n0 + wn * 32 + j * 8 + 2 * tig;
            float bx = 0.f, by = 0.f;
            if (HASB) { bx = bias[col]; by = bias[col + 1]; }
            long r0 = m0 + wm * 32 + mi * 16 + gid;
            float v0x = acc[mi][j][0] * alpha + bx, v0y = acc[mi][j][1] * alpha + by;
            float v1x = acc[mi][j][2] * alpha + bx, v1y = acc[mi][j][3] * alpha + by;
            if (OM == 0) {
                float* C = (float*)C0 + (long)blockIdx.z * cB;
                *(float2*)&C[r0 * (long)ldc + col] = make_float2(v0x, v0y);
                *(float2*)&C[(r0 + 8) * (long)ldc + col] = make_float2(v1x, v1y);
            } else if (OM == 1) {
                __half* C = (__half*)C0 + (long)blockIdx.z * cB;
                *(__half2*)&C[r0 * (long)ldc + col] = __floats2half2_rn(v0x, v0y);
                *(__half2*)&C[(r0 + 8) * (long)ldc + col] = __floats2half2_rn(v1x, v1y);
            } else {
                uint32_t* Ch = (uint32_t*)C0 + (long)blockIdx.z * cB;
                uint32_t* Cl = (uint32_t*)C1 + (long)blockIdx.z * cB;
                long wi = col >> 1;
                uint32_t h0, l0, h1, l1;
                split_bf2(make_float2(v0x, v0y), h0, l0);
                split_bf2(make_float2(v1x, v1y), h1, l1);
                Ch[r0 * (long)ldc + wi] = h0; Cl[r0 * (long)ldc + wi] = l0;
                Ch[(r0 + 8) * (long)ldc + wi] = h1; Cl[(r0 + 8) * (long)ldc + wi] = l1;
            }
        }
    }
}

// ---------------- kv post: rmsnorm latent + rope -> g_kfh (fp16) + g_kfv (tf32) ----------------
__global__ __launch_bounds__(128)
void kv_post(const float* __restrict__ freqs, const float* __restrict__ knw)
{
    int bs = blockIdx.x;
    int s = bs & (S_ - 1);
    int tid = threadIdx.x;
    const uint32_t* rh = gs_kvh + (long)bs * 288;
    const uint32_t* rl = gs_kvl + (long)bs * 288;

    float ss = 0.f;
    for (int wi = tid; wi < 256; wi += 128) {
        float2 p = up2(rh[wi], rl[wi]);
        ss += p.x * p.x + p.y * p.y;
    }
    __shared__ float red[128];
    red[tid] = ss;
    __syncthreads();
    for (int o = 64; o > 0; o >>= 1) {
        if (tid < o) red[tid] += red[tid + o];
        __syncthreads();
    }
    __shared__ float rinv;
    if (tid == 0) rinv = rsqrtf(red[0] * (1.0f / RK) + EPS_);
    __syncthreads();
    float rv = rinv;
    __half* oh = g_kfh + (long)bs * CD;
    float*  ov = g_kfv + (long)bs * RK;
    for (int wi = tid; wi < 256; wi += 128) {
        float2 p = up2(rh[wi], rl[wi]);
        float x0 = p.x * rv * knw[2 * wi];
        float x1 = p.y * rv * knw[2 * wi + 1];
        ov[2 * wi] = tf32r(x0); ov[2 * wi + 1] = tf32r(x1);
        *(__half2*)&oh[2 * wi] = __floats2half2_rn(x0, x1);
    }
    if (tid < 32) {
        float2 p = up2(rh[256 + tid], rl[256 + tid]);
        float f = freqs[(long)s * 32 + tid];
        float sn, cs;
        sincosf(f, &sn, &cs);
        *(__half2*)&oh[RK + 2 * tid] =
            __floats2half2_rn(p.x * cs - p.y * sn, p.x * sn + p.y * cs);
    }
}

// ---------------- q rope (pairs in, fp16 out, scaled) ----------------
__global__ __launch_bounds__(512)
void q_rope(const float* __restrict__ freqs)
{
    int bs = blockIdx.x;
    int s = bs & (S_ - 1);
    int tid = threadIdx.x;
    int h = tid >> 5, i = tid & 31;
    long wi = (long)bs * 1536 + h * 96 + 64 + i;
    float2 p = up2(gs_qh[wi], gs_ql[wi]);
    float f = freqs[(long)s * 32 + i];
    float sn, cs;
    sincosf(f, &sn, &cs);
    __half* o = g_qfh + ((long)bs * H_ + h) * CD + RK;
    *(__half2*)&o[2 * i] =
        __floats2half2_rn((p.x * cs - p.y * sn) * SCALE_, (p.x * sn + p.y * cs) * SCALE_);
}

// ---------------- flash MQA: fp16 scores + tf32 PV ----------------
// Block: 4 tokens x 16 heads = 64 q-rows. TK=32 keys/tile.
// sq fp16 64x(288w pitch 300); skh fp16 32x(288w pitch 300); sv fp32 32x(512 pitch 516);
// sP fp32 64x36 (stats cols 32..34).
#define SQW (64 * 300)
#define SKW (32 * 300)
#define SVW (32 * 516)
#define SPW (64 * 36)
#define FLASH_SMEM ((SQW + SKW + SVW + SPW) * 4)   // 190464 B

__global__ __launch_bounds__(256, 1)
void flash_tc()
{
    extern __shared__ uint32_t fsm[];
    uint32_t* sq  = fsm;
    uint32_t* skh = fsm + SQW;
    float*    sv  = (float*)(fsm + SQW + SKW);
    float*    sP  = (float*)(fsm + SQW + SKW + SVW);

    int qs = blockIdx.x * 4;
    int b  = blockIdx.y;
    int tid = threadIdx.x;
    int w = tid >> 5, lane = tid & 31, gid = lane >> 2, tig = lane & 3;
    int bS = b * S_;

    uint32_t squ = sm_u32(sq), sku = sm_u32(skh), svu = sm_u32(sv);
    const uint32_t* qw = (const uint32_t*)g_qfh;
    const uint32_t* kw = (const uint32_t*)g_kfh;
    const uint32_t* vw = (const uint32_t*)g_kfv;

    // prologue: q tile (64 rows x 72 chunks)
    for (int c = tid; c < 64 * 72; c += 256) {
        int row = c / 72, ch = c - row * 72;
        int tok = row >> 4, h = row & 15;
        CPA16(squ + (row * 300 + 4 * ch) * 4,
              &qw[((long)(bS + qs + tok) * H_ + h) * 288 + 4 * ch]);
    }
    // K/V tile 0
    for (int c = tid; c < 6400; c += 256) {
        if (c < 2304) {
            int r = c / 72, ch = c - r * 72;
            CPA16(sku + (r * 300 + 4 * ch) * 4, &kw[(long)(bS + r) * 288 + 4 * ch]);
        } else {
            int c2 = c - 2304;
            int r = c2 >> 7, ch = c2 & 127;
            CPA16(svu + (r * 516 + 4 * ch) * 4, &vw[(long)(bS + r) * 512 + 4 * ch]);
        }
    }
    CPCOMMIT();
    if (tid < 64) { sP[tid * 36 + 32] = -3.0e38f; sP[tid * 36 + 33] = 0.f; }

    float oacc[4][8][4];
#pragma unroll
    for (int rg = 0; rg < 4; rg++)
#pragma unroll
        for (int j = 0; j < 8; j++)
#pragma unroll
            for (int e = 0; e < 4; e++) oacc[rg][j][e] = 0.f;

    int ntk = qs / 32 + 1;

    for (int kt = 0; kt < ntk; kt++) {
        int t0 = kt * 32;
        CPWAIT(0);
        __syncthreads();

        // ---- scores: warps 0..3, 16 rows x 32 keys, fp16 k16 x 36 chunks ----
        if (w < 4) {
            int rb = w * 16;
            const uint32_t* r0p = sq + (rb + gid) * 300;
            const uint32_t* r1p = sq + (rb + gid + 8) * 300;
            float sc[4][4];
#pragma unroll
            for (int j = 0; j < 4; j++)
#pragma unroll
                for (int e = 0; e < 4; e++) sc[j][e] = 0.f;
#pragma unroll 4
            for (int kk = 0; kk < 36; kk++) {
                int kc = kk * 8;
                uint32_t a0 = r0p[kc + tig];
                uint32_t a1 = r1p[kc + tig];
                uint32_t a2 = r0p[kc + tig + 4];
                uint32_t a3 = r1p[kc + tig + 4];
#pragma unroll
                for (int j = 0; j < 4; j++) {
                    int nb = j * 8 + gid;
                    uint32_t b0 = skh[nb * 300 + kc + tig];
                    uint32_t b1 = skh[nb * 300 + kc + tig + 4];
                    mma_f16(sc[j], a0, a1, a2, a3, b0, b1);
                }
            }
#pragma unroll
            for (int j = 0; j < 4; j++) {
                int c0 = j * 8 + 2 * tig;
                *(float2*)&sP[(rb + gid) * 36 + c0] = make_float2(sc[j][0], sc[j][1]);
                *(float2*)&sP[(rb + gid + 8) * 36 + c0] = make_float2(sc[j][2], sc[j][3]);
            }
        }
        __syncthreads();

        // ---- online softmax (64 threads); causal mask ----
        if (tid < 64) {
            int row = tid;
            int spos = qs + (row >> 4);
            float* pr = sP + row * 36;
            float v[32];
            float mo = pr[32], mx = mo;
#pragma unroll
            for (int j = 0; j < 32; j++) {
                float x = pr[j];
                if (t0 + j > spos) x = -1.0e30f;
                v[j] = x;
                mx = fmaxf(mx, x);
            }
            float al = __expf(mo - mx);
            float sum = 0.f;
#pragma unroll
            for (int j = 0; j < 32; j++) {
                float p = __expf(v[j] - mx);
                sum += p;
                pr[j] = tf32r(p);
            }
            pr[32] = mx;
            pr[33] = pr[33] * al + sum;
            pr[34] = al;
        }
        __syncthreads();

        // ---- PV (tf32): all 8 warps, 64 rows x 64 V-cols each ----
        {
            float al0[4], al1[4];
#pragma unroll
            for (int rg = 0; rg < 4; rg++) {
                al0[rg] = sP[(rg * 16 + gid) * 36 + 34];
                al1[rg] = sP[(rg * 16 + gid + 8) * 36 + 34];
            }
#pragma unroll
            for (int rg = 0; rg < 4; rg++)
#pragma unroll
                for (int j = 0; j < 8; j++) {
                    oacc[rg][j][0] *= al0[rg]; oacc[rg][j][1] *= al0[rg];
                    oacc[rg][j][2] *= al1[rg]; oacc[rg][j][3] *= al1[rg];
                }
#pragma unroll
            for (int kk = 0; kk < 4; kk++) {
                int kc = kk * 8;
                uint32_t A0[4], A1[4], A2[4], A3[4];
#pragma unroll
                for (int rg = 0; rg < 4; rg++) {
                    A0[rg] = __float_as_uint(sP[(rg * 16 + gid) * 36 + kc + tig]);
                    A1[rg] = __float_as_uint(sP[(rg * 16 + gid + 8) * 36 + kc + tig]);
                    A2[rg] = __float_as_uint(sP[(rg * 16 + gid) * 36 + kc + tig + 4]);
                    A3[rg] = __float_as_uint(sP[(rg * 16 + gid + 8) * 36 + kc + tig + 4]);
                }
#pragma unroll
                for (int j = 0; j < 8; j++) {
                    int col = w * 64 + j * 8 + gid;
                    uint32_t b0 = __float_as_uint(sv[(kc + tig) * 516 + col]);
                    uint32_t b1 = __float_as_uint(sv[(kc + tig + 4) * 516 + col]);
#pragma unroll
                    for (int rg = 0; rg < 4; rg++)
                        mma_tf32(oacc[rg][j], A0[rg], A1[rg], A2[rg], A3[rg], b0, b1);
                }
            }
        }
        __syncthreads();

        if (kt + 1 < ntk) {
            int tn = t0 + 32;
            for (int c = tid; c < 6400; c += 256) {
                if (c < 2304) {
                    int r = c / 72, ch = c - r * 72;
                    CPA16(sku + (r * 300 + 4 * ch) * 4, &kw[(long)(bS + tn + r) * 288 + 4 * ch]);
                } else {
                    int c2 = c - 2304;
                    int r = c2 >> 7, ch = c2 & 127;
                    CPA16(svu + (r * 516 + 4 * ch) * 4, &vw[(long)(bS + tn + r) * 512 + 4 * ch]);
                }
            }
        }
        CPCOMMIT();
    }

    // ---- epilogue: normalize + write bf16 pairs for v-up GEMM ----
#pragma unroll
    for (int rg = 0; rg < 4; rg++) {
        float l0 = 1.f / sP[(rg * 16 + gid) * 36 + 33];
        float l1 = 1.f / sP[(rg * 16 + gid + 8) * 36 + 33];
        long base = (long)(bS + qs + rg) * 4096;
        long w0 = base + gid * 256 + w * 32;
        long w1 = base + (gid + 8) * 256 + w * 32;
#pragma unroll
        for (int j = 0; j < 8; j++) {
            uint32_t h0, lo0, h1, lo1;
            split_bf2(make_float2(oacc[rg][j][0] * l0, oacc[rg][j][1] * l0), h0, lo0);
            split_bf2(make_float2(oacc[rg][j][2] * l1, oacc[rg][j][3] * l1), h1, lo1);
            gs_olh[w0 + j * 4 + tig] = h0; gs_oll[w0 + j * 4 + tig] = lo0;
            gs_olh[w1 + j * 4 + tig] = h1; gs_oll[w1 + j * 4 + tig] = lo1;
        }
    }
}

// ---------------- launch ----------------
extern "C" void kernel_launch(void* const* d_in, const int* in_sizes, int n_in,
                              void* d_out, int out_size)
{
    const float* x      = (const float*)d_in[0];
    const float* freqs  = (const float*)d_in[1];
    // d_in[2] = mask (causal handled analytically)
    const float* wq_w   = (const float*)d_in[3];
    const float* wq_b   = (const float*)d_in[4];
    const float* wkva_w = (const float*)d_in[5];
    const float* wkva_b = (const float*)d_in[6];
    const float* knw    = (const float*)d_in[7];
    const float* wkvb   = (const float*)d_in[8];
    const float* wo_w   = (const float*)d_in[9];
    const float* wo_b   = (const float*)d_in[10];
    float* out = (float*)d_out;

    void *xh, *xl, *wqh, *wql, *wah, *wal, *woh, *wol;
    void *qh, *ql, *kvh, *kvl, *olh, *oll, *ovh, *ovl;
    void *bTh, *bTl, *bVh, *bVl, *qfh, *kfh, *kfv;
    cudaGetSymbolAddress(&xh, gs_xh);   cudaGetSymbolAddress(&xl, gs_xl);
    cudaGetSymbolAddress(&wqh, gs_wqh); cudaGetSymbolAddress(&wql, gs_wql);
    cudaGetSymbolAddress(&wah, gs_wah); cudaGetSymbolAddress(&wal, gs_wal);
    cudaGetSymbolAddress(&woh, gs_woh); cudaGetSymbolAddress(&wol, gs_wol);
    cudaGetSymbolAddress(&qh, gs_qh);   cudaGetSymbolAddress(&ql, gs_ql);
    cudaGetSymbolAddress(&kvh, gs_kvh); cudaGetSymbolAddress(&kvl, gs_kvl);
    cudaGetSymbolAddress(&olh, gs_olh); cudaGetSymbolAddress(&oll, gs_oll);
    cudaGetSymbolAddress(&ovh, gs_ovh); cudaGetSymbolAddress(&ovl, gs_ovl);
    cudaGetSymbolAddress(&bTh, gs_bTh); cudaGetSymbolAddress(&bTl, gs_bTl);
    cudaGetSymbolAddress(&bVh, gs_bVh); cudaGetSymbolAddress(&bVl, gs_bVl);
    cudaGetSymbolAddress(&qfh, g_qfh);  cudaGetSymbolAddress(&kfh, g_kfh);
    cudaGetSymbolAddress(&kfv, g_kfv);

    cudaFuncSetAttribute(flash_tc, cudaFuncAttributeMaxDynamicSharedMemorySize, FLASH_SMEM);
    cudaFuncSetAttribute(gemm_ps<2, true>,  cudaFuncAttributeMaxDynamicSharedMemorySize, GEMM_SMEM);
    cudaFuncSetAttribute(gemm_ps<1, false>, cudaFuncAttributeMaxDynamicSharedMemorySize, GEMM_SMEM);
    cudaFuncSetAttribute(gemm_ps<2, false>, cudaFuncAttributeMaxDynamicSharedMemorySize, GEMM_SMEM);
    cudaFuncSetAttribute(gemm_ps<0, true>,  cudaFuncAttributeMaxDynamicSharedMemorySize, GEMM_SMEM);

    // 0) pre-split inputs
    split_pairs<<<16384, 256>>>((const float2*)x, (uint32_t*)xh, (uint32_t*)xl, BS * 1024);
    split_pairs<<<12288, 256>>>((const float2*)wq_w, (uint32_t*)wqh, (uint32_t*)wql, 3072 * 1024);
    split_pairs<<<2304, 256>>>((const float2*)wkva_w, (uint32_t*)wah, (uint32_t*)wal, 576 * 1024);
    split_pairs<<<8192, 256>>>((const float2*)wo_w, (uint32_t*)woh, (uint32_t*)wol, 2048 * 1024);
    split_wkvb_nope<<<2048, 256>>>(wkvb);
    split_wkvb_v<<<2048, 256>>>(wkvb);

    // 1) kv = x @ wkv_a^T + b -> split pairs
    gemm_ps<2, true><<<dim3(9, 32, 1), 256, GEMM_SMEM>>>(
        1024, (uint32_t*)xh, (uint32_t*)xl, 1024, 0,
        (uint32_t*)wah, (uint32_t*)wal, 1024, 0,
        kvh, kvl, 288, 0, wkva_b, 1.f);

    // 2) rmsnorm + rope K -> g_kfh / g_kfv
    kv_post<<<BS, 128>>>(freqs, knw);

    // 3) q = x @ wq^T + b -> split pairs
    gemm_ps<2, true><<<dim3(48, 32, 1), 256, GEMM_SMEM>>>(
        1024, (uint32_t*)xh, (uint32_t*)xl, 1024, 0,
        (uint32_t*)wqh, (uint32_t*)wql, 1024, 0,
        qh, ql, 1536, 0, wq_b, 1.f);

    // 4) rope q_pe (scaled, fp16) -> g_qfh[..., 512:576]
    q_rope<<<BS, 512>>>(freqs);

    // 5) q_absorbed per head (vs transposed wkvb_nope), scaled, fp16 out
    gemm_ps<1, false><<<dim3(8, 32, H_), 256, GEMM_SMEM>>>(
        64, (uint32_t*)qh, (uint32_t*)ql, 1536, 96,
        (uint32_t*)bTh, (uint32_t*)bTl, 64, 32768,
        qfh, nullptr, H_ * CD, CD, nullptr, SCALE_);

    // 6) causal flash MQA -> split pairs g_ol
    flash_tc<<<dim3(S_ / 4, B_), 256, FLASH_SMEM>>>();

    // 7) per-head V up-projection -> split pairs g_ov
    gemm_ps<2, false><<<dim3(2, 32, H_), 256, GEMM_SMEM>>>(
        256, (uint32_t*)olh, (uint32_t*)oll, 4096, 256,
        (uint32_t*)bVh, (uint32_t*)bVl, 256, 32768,
        ovh, ovl, 1024, 64, nullptr, 1.f);

    // 8) final: g_ov @ wo^T + wo_b -> out (fp32)
    gemm_ps<0, true><<<dim3(32, 32, 1), 256, GEMM_SMEM>>>(
        1024, (uint32_t*)ovh, (uint32_t*)ovl, 1024, 0,
        (uint32_t*)woh, (uint32_t*)wol, 1024, 0,
        out, nullptr, 2048, 0, wo_b, 1.f);
}